// round 11
// baseline (speedup 1.0000x reference)
#include <cuda_runtime.h>
#include <cuda_bf16.h>
#include <math.h>

#define B_ 4
#define T_ 2048
#define D_ 256
#define H_ 4
#define HD_ 64
#define L_ 2
#define NQ_ 128

// ---------------- device scratch ----------------
__device__ float    g_x  [B_*T_*D_];
__device__ float    g_h  [B_*T_*D_];
__device__ float    g_qkv[B_*T_*3*D_];
__device__ unsigned g_qkb[(size_t)B_*T_*256];          // roped q,k packed bf16
__device__ unsigned g_vTb[(size_t)B_*H_*HD_*1024];     // V^T bf16: [b*H+h][d][t/2]
__device__ float    g_ffn[(size_t)B_*T_*4*D_];
__device__ float    g_sel[B_*NQ_*D_];
__device__ float4   g_ropec[T_*16];                    // (cos0,sin0,cos1,sin1) per (t, j)
__device__ float    g_oqT[D_*NQ_];
__device__ float    g_bits[B_*NQ_];

// ---------------- helpers ----------------
__device__ __forceinline__ unsigned f2tf(float f) {
    unsigned u; asm("cvt.rna.tf32.f32 %0, %1;" : "=r"(u) : "f"(f)); return u;
}
__device__ __forceinline__ unsigned pkbf(float lo, float hi) {
    unsigned r; asm("cvt.rn.bf16x2.f32 %0, %1, %2;" : "=r"(r) : "f"(hi), "f"(lo)); return r;
}
__device__ __forceinline__ void mma_tf32(float* c, const unsigned* a, const unsigned* b) {
    asm volatile("mma.sync.aligned.m16n8k8.row.col.f32.tf32.tf32.f32 "
        "{%0,%1,%2,%3}, {%4,%5,%6,%7}, {%8,%9}, {%0,%1,%2,%3};"
        : "+f"(c[0]), "+f"(c[1]), "+f"(c[2]), "+f"(c[3])
        : "r"(a[0]), "r"(a[1]), "r"(a[2]), "r"(a[3]), "r"(b[0]), "r"(b[1]));
}
__device__ __forceinline__ void mma_bf16(float* c, const unsigned* a, const unsigned* b) {
    asm volatile("mma.sync.aligned.m16n8k16.row.col.f32.bf16.bf16.f32 "
        "{%0,%1,%2,%3}, {%4,%5,%6,%7}, {%8,%9}, {%0,%1,%2,%3};"
        : "+f"(c[0]), "+f"(c[1]), "+f"(c[2]), "+f"(c[3])
        : "r"(a[0]), "r"(a[1]), "r"(a[2]), "r"(a[3]), "r"(b[0]), "r"(b[1]));
}
__device__ __forceinline__ void cp16(void* sp, const void* gp) {
    unsigned s = (unsigned)__cvta_generic_to_shared(sp);
    asm volatile("cp.async.cg.shared.global [%0], [%1], 16;" :: "r"(s), "l"(gp));
}
__device__ __forceinline__ void cp_commit() { asm volatile("cp.async.commit_group;"); }
template<int N> __device__ __forceinline__ void cp_wait() {
    asm volatile("cp.async.wait_group %0;" :: "n"(N));
}

// ---------------- embed ----------------
__global__ void embed_kernel(const int* __restrict__ tokens,
                             const float* __restrict__ emb,
                             float* __restrict__ x) {
    int i = blockIdx.x * 256 + threadIdx.x;
    if (i >= B_*T_*D_) return;
    int d = i & (D_-1);
    int bt = i >> 8;
    x[i] = emb[tokens[bt]*D_ + d];
}

// ---------------- rope table (once) ----------------
__global__ void rope_tab_kernel(float4* __restrict__ tab) {
    int idx = blockIdx.x * 256 + threadIdx.x;     // T_*16
    if (idx >= T_*16) return;
    int t = idx >> 4, j = idx & 15;
    float i0 = powf(10000.f, -(float)(2*j  ) * (1.f/32.f));
    float i1 = powf(10000.f, -(float)(2*j+1) * (1.f/32.f));
    float s0, c0, s1, c1;
    sincosf((float)t * i0, &s0, &c0);
    sincosf((float)t * i1, &s1, &c1);
    tab[idx] = make_float4(c0, s0, c1, s1);
}

// ---------------- layernorm: warp per row ----------------
__global__ void ln_kernel(const float* __restrict__ x,
                          const float* __restrict__ w,
                          const float* __restrict__ b,
                          float* __restrict__ y) {
    int row = blockIdx.x * 8 + (threadIdx.x >> 5);
    int lane = threadIdx.x & 31;
    const float* xr = x + (size_t)row * D_;
    float4 v0 = *(const float4*)(xr + lane*4);
    float4 v1 = *(const float4*)(xr + 128 + lane*4);
    float s = v0.x+v0.y+v0.z+v0.w + v1.x+v1.y+v1.z+v1.w;
    #pragma unroll
    for (int o = 16; o > 0; o >>= 1) s += __shfl_xor_sync(0xffffffffu, s, o);
    float mean = s * (1.f/256.f);
    float d0=v0.x-mean, d1=v0.y-mean, d2=v0.z-mean, d3=v0.w-mean;
    float d4=v1.x-mean, d5=v1.y-mean, d6=v1.z-mean, d7=v1.w-mean;
    float s2 = d0*d0+d1*d1+d2*d2+d3*d3+d4*d4+d5*d5+d6*d6+d7*d7;
    #pragma unroll
    for (int o = 16; o > 0; o >>= 1) s2 += __shfl_xor_sync(0xffffffffu, s2, o);
    float rs = rsqrtf(s2 * (1.f/256.f) + 1e-5f);
    float4 w0 = *(const float4*)(w + lane*4), w1 = *(const float4*)(w + 128 + lane*4);
    float4 b0 = *(const float4*)(b + lane*4), b1 = *(const float4*)(b + 128 + lane*4);
    float* yr = y + (size_t)row * D_;
    *(float4*)(yr + lane*4)       = make_float4(d0*rs*w0.x+b0.x, d1*rs*w0.y+b0.y, d2*rs*w0.z+b0.z, d3*rs*w0.w+b0.w);
    *(float4*)(yr + 128 + lane*4) = make_float4(d4*rs*w1.x+b1.x, d5*rs*w1.y+b1.y, d6*rs*w1.z+b1.z, d7*rs*w1.w+b1.w);
}

// ---------------- tf32 tensor-core GEMM (batched-capable) ----------------
// OUT: 0 plain (+bias,+resid), 1 +GELU, 3 transposed scores epilogue -> C[b][col][t]
template<int OUT, bool RES>
__global__ __launch_bounds__(256)
void gemm_tf32_kernel(const float* __restrict__ A, const float* __restrict__ W,
                      const float* __restrict__ bias, const float* __restrict__ resid,
                      float* __restrict__ C, int M, int N, int K, float alpha,
                      size_t sA, size_t sW, size_t sC) {
    A += (size_t)blockIdx.z * sA;
    W += (size_t)blockIdx.z * sW;
    C += (size_t)blockIdx.z * sC;
    __shared__ unsigned Ast[2][16][132];
    __shared__ unsigned Ws [2][16][132];
    int tid = threadIdx.x;
    int w = tid >> 5, lane = tid & 31;
    int g = lane >> 2, q = lane & 3;
    int wm = (w >> 2) * 64, wn = (w & 3) * 32;
    int bm = blockIdx.y * 128, bn = blockIdx.x * 128;

    float acc[4][4][4] = {};
    float4 aR[2], bR[2];

    #pragma unroll
    for (int i = 0; i < 2; i++) {
        int fi = tid + i*256;
        int r = fi >> 2, kg = (fi & 3) << 2;
        aR[i] = *(const float4*)(A + (size_t)(bm + r) * K + kg);
        int r2 = fi >> 5, cg = (fi & 31) << 2;
        bR[i] = *(const float4*)(W + (size_t)r2 * N + bn + cg);
    }
    #pragma unroll
    for (int i = 0; i < 2; i++) {
        int fi = tid + i*256;
        int r = fi >> 2, kg = (fi & 3) << 2;
        Ast[0][kg+0][r] = f2tf(aR[i].x); Ast[0][kg+1][r] = f2tf(aR[i].y);
        Ast[0][kg+2][r] = f2tf(aR[i].z); Ast[0][kg+3][r] = f2tf(aR[i].w);
        int r2 = fi >> 5, cg = (fi & 31) << 2;
        Ws[0][r2][cg+0] = f2tf(bR[i].x); Ws[0][r2][cg+1] = f2tf(bR[i].y);
        Ws[0][r2][cg+2] = f2tf(bR[i].z); Ws[0][r2][cg+3] = f2tf(bR[i].w);
    }
    __syncthreads();

    int nT = K >> 4;
    for (int t = 0; t < nT; t++) {
        int cur = t & 1;
        if (t + 1 < nT) {
            int k0 = (t + 1) << 4;
            #pragma unroll
            for (int i = 0; i < 2; i++) {
                int fi = tid + i*256;
                int r = fi >> 2, kg = (fi & 3) << 2;
                aR[i] = *(const float4*)(A + (size_t)(bm + r) * K + k0 + kg);
                int r2 = fi >> 5, cg = (fi & 31) << 2;
                bR[i] = *(const float4*)(W + (size_t)(k0 + r2) * N + bn + cg);
            }
        }
        #pragma unroll
        for (int ks = 0; ks < 16; ks += 8) {
            unsigned af[4][4], bf[4][2];
            #pragma unroll
            for (int mf = 0; mf < 4; mf++) {
                int r0 = wm + mf*16;
                af[mf][0] = Ast[cur][ks+q  ][r0+g  ];
                af[mf][1] = Ast[cur][ks+q  ][r0+g+8];
                af[mf][2] = Ast[cur][ks+q+4][r0+g  ];
                af[mf][3] = Ast[cur][ks+q+4][r0+g+8];
            }
            #pragma unroll
            for (int nf = 0; nf < 4; nf++) {
                int c0 = wn + nf*8;
                bf[nf][0] = Ws[cur][ks+q  ][c0+g];
                bf[nf][1] = Ws[cur][ks+q+4][c0+g];
            }
            #pragma unroll
            for (int mf = 0; mf < 4; mf++)
                #pragma unroll
                for (int nf = 0; nf < 4; nf++)
                    mma_tf32(acc[mf][nf], af[mf], bf[nf]);
        }
        if (t + 1 < nT) {
            int nb = cur ^ 1;
            #pragma unroll
            for (int i = 0; i < 2; i++) {
                int fi = tid + i*256;
                int r = fi >> 2, kg = (fi & 3) << 2;
                Ast[nb][kg+0][r] = f2tf(aR[i].x); Ast[nb][kg+1][r] = f2tf(aR[i].y);
                Ast[nb][kg+2][r] = f2tf(aR[i].z); Ast[nb][kg+3][r] = f2tf(aR[i].w);
                int r2 = fi >> 5, cg = (fi & 31) << 2;
                Ws[nb][r2][cg+0] = f2tf(bR[i].x); Ws[nb][r2][cg+1] = f2tf(bR[i].y);
                Ws[nb][r2][cg+2] = f2tf(bR[i].z); Ws[nb][r2][cg+3] = f2tf(bR[i].w);
            }
        }
        __syncthreads();
    }

    if (OUT == 3) {
        // transposed scores: C[(b*NQ + col)*T + t], r = b*T + t
        #pragma unroll
        for (int mf = 0; mf < 4; mf++) {
            #pragma unroll
            for (int i = 0; i < 2; i++) {
                int r = bm + wm + mf*16 + g + i*8;
                int bb = r >> 11, tt = r & (T_-1);
                #pragma unroll
                for (int nf = 0; nf < 4; nf++) {
                    int c = bn + wn + nf*8 + 2*q;
                    C[((size_t)(bb*NQ_ + c  ))*T_ + tt] = acc[mf][nf][i*2+0] * alpha;
                    C[((size_t)(bb*NQ_ + c+1))*T_ + tt] = acc[mf][nf][i*2+1] * alpha;
                }
            }
        }
        return;
    }

    #pragma unroll
    for (int mf = 0; mf < 4; mf++) {
        #pragma unroll
        for (int i = 0; i < 2; i++) {
            int r = bm + wm + mf*16 + g + i*8;
            #pragma unroll
            for (int nf = 0; nf < 4; nf++) {
                int c = bn + wn + nf*8 + 2*q;
                float v0 = acc[mf][nf][i*2+0] * alpha + (bias ? bias[c]   : 0.f);
                float v1 = acc[mf][nf][i*2+1] * alpha + (bias ? bias[c+1] : 0.f);
                if (OUT == 1) {
                    v0 = 0.5f * v0 * (1.f + erff(v0 * 0.70710678118654752f));
                    v1 = 0.5f * v1 * (1.f + erff(v1 * 0.70710678118654752f));
                }
                if (RES) {
                    v0 += resid[(size_t)r * N + c];
                    v1 += resid[(size_t)r * N + c + 1];
                }
                *(float2*)(C + (size_t)r * N + c) = make_float2(v0, v1);
            }
        }
    }
}

// ---------------- fused rope(table)+pack + V transpose ----------------
// grid (T/64, H, B), 256 threads
__global__ void ropevt_kernel(const float* __restrict__ qkv,
                              const float4* __restrict__ ropec,
                              unsigned* __restrict__ qkb, unsigned* __restrict__ vT) {
    __shared__ float vs[64][65];
    int t0 = blockIdx.x * 64, h = blockIdx.y, b = blockIdx.z;
    int tid = threadIdx.x;
    // V transpose
    const float* src = qkv + ((size_t)(b*T_ + t0)) * (3*D_) + 2*D_ + h*HD_;
    #pragma unroll
    for (int i = 0; i < 16; i++) {
        int idx = tid + i*256;
        int tl = idx >> 6, d = idx & 63;
        vs[d][tl] = src[(size_t)tl * (3*D_) + d];
    }
    // rope: 64 tokens x 16 j x 2 qk = 2048 items
    #pragma unroll
    for (int i = 0; i < 8; i++) {
        int idx = tid + i*256;
        int j = idx & 15, qk = (idx >> 4) & 1, tl = idx >> 5;
        int t = t0 + tl, bt = b*T_ + t;
        const float* s2 = qkv + (size_t)bt * (3*D_) + qk*D_ + h*HD_;
        float2 a = *(const float2*)(s2 + 2*j);
        float2 p = *(const float2*)(s2 + 2*j + 32);
        float4 cs = ropec[t*16 + j];
        unsigned* dst = qkb + (size_t)bt * 256 + qk*128 + h*32;
        dst[j]      = pkbf(a.x*cs.x - p.x*cs.y, a.y*cs.z - p.y*cs.w);
        dst[j + 16] = pkbf(p.x*cs.x + a.x*cs.y, p.y*cs.z + a.y*cs.w);
    }
    __syncthreads();
    unsigned* dst = vT + ((size_t)((b*H_ + h)*HD_)) * 1024 + (t0 >> 1);
    #pragma unroll
    for (int i = 0; i < 8; i++) {
        int idx = tid + i*256;
        int d = idx >> 5, wp = idx & 31;
        dst[(size_t)d * 1024 + wp] = pkbf(vs[d][2*wp], vs[d][2*wp+1]);
    }
}

// ---------------- bf16 flash attention (R10 core) ----------------
#define ATTN_SMEM4 ((128*36 + 4*64*36) * 4)
__global__ __launch_bounds__(256)
void attn_bf16_kernel(const unsigned* __restrict__ qkb, const unsigned* __restrict__ vT,
                      float* __restrict__ out) {
    extern __shared__ unsigned sm[];
    unsigned* Qw  = sm;
    unsigned* Kw0 = sm + 128*36;
    unsigned* Kw1 = Kw0 + 64*36;
    unsigned* Vw0 = Kw1 + 64*36;
    unsigned* Vw1 = Vw0 + 64*36;
    int qt = (T_/128 - 1) - blockIdx.x;
    int h = blockIdx.y, b = blockIdx.z;
    int tid = threadIdx.x;
    int w = tid >> 5, lane = tid & 31, g = lane >> 2, q = lane & 3;
    int r0 = w * 16;

    const unsigned* qrow = qkb + ((size_t)(b*T_) + qt*128) * 256 + h*32;
    const unsigned* krow = qkb + (size_t)(b*T_) * 256 + 128 + h*32;
    const unsigned* vrow = vT + ((size_t)((b*H_ + h)*HD_)) * 1024;

    #pragma unroll
    for (int i = 0; i < 4; i++) {
        int idx = tid + i*256;
        int r = idx >> 3, c = (idx & 7) << 2;
        cp16(&Qw[r*36 + c], qrow + (size_t)r*256 + c);
    }
    #pragma unroll
    for (int i = 0; i < 2; i++) {
        int idx = tid + i*256;
        int r = idx >> 3, c = (idx & 7) << 2;
        cp16(&Kw0[r*36 + c], krow + (size_t)r*256 + c);
        cp16(&Vw0[r*36 + c], vrow + (size_t)r*1024 + c);
    }
    cp_commit();

    float m0 = -INFINITY, m1 = -INFINITY;
    float l0 = 0.f, l1 = 0.f;
    float O[8][4] = {};
    int ktmax = 2*qt + 1;
    int rg0 = qt*128 + r0 + g, rg1 = rg0 + 8;

    for (int kt = 0; kt <= ktmax; kt++) {
        unsigned* Kc = (kt & 1) ? Kw1 : Kw0;
        unsigned* Vc = (kt & 1) ? Vw1 : Vw0;
        if (kt < ktmax) {
            unsigned* Kn = (kt & 1) ? Kw0 : Kw1;
            unsigned* Vn = (kt & 1) ? Vw0 : Vw1;
            const unsigned* krow2 = krow + (size_t)(kt+1)*64*256;
            const unsigned* vrow2 = vrow + (kt+1)*32;
            #pragma unroll
            for (int i = 0; i < 2; i++) {
                int idx = tid + i*256;
                int r = idx >> 3, c = (idx & 7) << 2;
                cp16(&Kn[r*36 + c], krow2 + (size_t)r*256 + c);
                cp16(&Vn[r*36 + c], vrow2 + (size_t)r*1024 + c);
            }
            cp_commit();
            cp_wait<1>();
        } else {
            cp_wait<0>();
        }
        __syncthreads();

        float S[8][4] = {};
        #pragma unroll
        for (int ss = 0; ss < 4; ss++) {
            unsigned af[4];
            af[0] = Qw[(r0+g  )*36 + ss*8 + q    ];
            af[1] = Qw[(r0+g+8)*36 + ss*8 + q    ];
            af[2] = Qw[(r0+g  )*36 + ss*8 + q + 4];
            af[3] = Qw[(r0+g+8)*36 + ss*8 + q + 4];
            #pragma unroll
            for (int nf = 0; nf < 8; nf++) {
                unsigned bf[2];
                bf[0] = Kc[(nf*8+g)*36 + ss*8 + q    ];
                bf[1] = Kc[(nf*8+g)*36 + ss*8 + q + 4];
                mma_bf16(S[nf], af, bf);
            }
        }

        #pragma unroll
        for (int nf = 0; nf < 8; nf++) {
            S[nf][0] *= 0.125f; S[nf][1] *= 0.125f;
            S[nf][2] *= 0.125f; S[nf][3] *= 0.125f;
        }
        if (kt >= 2*qt) {
            #pragma unroll
            for (int nf = 0; nf < 8; nf++) {
                int cg = kt*64 + nf*8 + 2*q;
                if (cg   > rg0) S[nf][0] = -INFINITY;
                if (cg+1 > rg0) S[nf][1] = -INFINITY;
                if (cg   > rg1) S[nf][2] = -INFINITY;
                if (cg+1 > rg1) S[nf][3] = -INFINITY;
            }
        }
        float mxa = -INFINITY, mxb = -INFINITY;
        #pragma unroll
        for (int nf = 0; nf < 8; nf++) {
            mxa = fmaxf(mxa, fmaxf(S[nf][0], S[nf][1]));
            mxb = fmaxf(mxb, fmaxf(S[nf][2], S[nf][3]));
        }
        mxa = fmaxf(mxa, __shfl_xor_sync(0xffffffffu, mxa, 1));
        mxa = fmaxf(mxa, __shfl_xor_sync(0xffffffffu, mxa, 2));
        mxb = fmaxf(mxb, __shfl_xor_sync(0xffffffffu, mxb, 1));
        mxb = fmaxf(mxb, __shfl_xor_sync(0xffffffffu, mxb, 2));
        float nm0 = fmaxf(m0, mxa), nm1 = fmaxf(m1, mxb);
        float rf0 = __expf(m0 - nm0), rf1 = __expf(m1 - nm1);
        float sa = 0.f, sb = 0.f;
        #pragma unroll
        for (int nf = 0; nf < 8; nf++) {
            S[nf][0] = __expf(S[nf][0] - nm0);
            S[nf][1] = __expf(S[nf][1] - nm0);
            S[nf][2] = __expf(S[nf][2] - nm1);
            S[nf][3] = __expf(S[nf][3] - nm1);
            sa += S[nf][0] + S[nf][1];
            sb += S[nf][2] + S[nf][3];
        }
        sa += __shfl_xor_sync(0xffffffffu, sa, 1);
        sa += __shfl_xor_sync(0xffffffffu, sa, 2);
        sb += __shfl_xor_sync(0xffffffffu, sb, 1);
        sb += __shfl_xor_sync(0xffffffffu, sb, 2);
        l0 = l0 * rf0 + sa;  l1 = l1 * rf1 + sb;
        m0 = nm0;            m1 = nm1;
        #pragma unroll
        for (int nf = 0; nf < 8; nf++) {
            O[nf][0] *= rf0; O[nf][1] *= rf0;
            O[nf][2] *= rf1; O[nf][3] *= rf1;
        }
        #pragma unroll
        for (int ss = 0; ss < 4; ss++) {
            unsigned pa[4];
            pa[0] = pkbf(S[2*ss  ][0], S[2*ss  ][1]);
            pa[1] = pkbf(S[2*ss  ][2], S[2*ss  ][3]);
            pa[2] = pkbf(S[2*ss+1][0], S[2*ss+1][1]);
            pa[3] = pkbf(S[2*ss+1][2], S[2*ss+1][3]);
            #pragma unroll
            for (int nf = 0; nf < 8; nf++) {
                unsigned bf[2];
                bf[0] = Vc[(nf*8+g)*36 + ss*8 + q    ];
                bf[1] = Vc[(nf*8+g)*36 + ss*8 + q + 4];
                mma_bf16(O[nf], pa, bf);
            }
        }
        __syncthreads();
    }

    float inv0 = 1.f / l0, inv1 = 1.f / l1;
    float* ob = out + ((size_t)(b*T_) + qt*128 + r0 + g) * D_ + h*HD_;
    #pragma unroll
    for (int nf = 0; nf < 8; nf++) {
        int c = nf*8 + 2*q;
        *(float2*)(ob + c)        = make_float2(O[nf][0]*inv0, O[nf][1]*inv0);
        *(float2*)(ob + 8*D_ + c) = make_float2(O[nf][2]*inv1, O[nf][3]*inv1);
    }
}

// ---------------- oq transpose ----------------
__global__ void oqT_kernel(const float* __restrict__ oq, float* __restrict__ oqT) {
    int idx = blockIdx.x * 256 + threadIdx.x;
    if (idx >= NQ_*D_) return;
    int r = idx >> 8, c = idx & 255;
    oqT[c*NQ_ + r] = oq[idx];
}

// ---------------- in-place row softmax on p[bq][t] ----------------
__global__ void qsoftmax_rows(float* __restrict__ p) {
    float* pr = p + (size_t)blockIdx.x * T_;
    int tid = threadIdx.x;
    __shared__ float red[8];
    float4 a = *(const float4*)(pr + tid*8);
    float4 b = *(const float4*)(pr + tid*8 + 4);
    float mx = fmaxf(fmaxf(fmaxf(a.x,a.y),fmaxf(a.z,a.w)),
                     fmaxf(fmaxf(b.x,b.y),fmaxf(b.z,b.w)));
    #pragma unroll
    for (int o = 16; o > 0; o >>= 1) mx = fmaxf(mx, __shfl_xor_sync(0xffffffffu, mx, o));
    if ((tid & 31) == 0) red[tid >> 5] = mx;
    __syncthreads();
    float bmax = -INFINITY;
    #pragma unroll
    for (int i = 0; i < 8; i++) bmax = fmaxf(bmax, red[i]);
    a.x = expf(a.x-bmax); a.y = expf(a.y-bmax); a.z = expf(a.z-bmax); a.w = expf(a.w-bmax);
    b.x = expf(b.x-bmax); b.y = expf(b.y-bmax); b.z = expf(b.z-bmax); b.w = expf(b.w-bmax);
    float s = a.x+a.y+a.z+a.w + b.x+b.y+b.z+b.w;
    __syncthreads();
    #pragma unroll
    for (int o = 16; o > 0; o >>= 1) s += __shfl_xor_sync(0xffffffffu, s, o);
    if ((tid & 31) == 0) red[tid >> 5] = s;
    __syncthreads();
    float bs = 0.f;
    #pragma unroll
    for (int i = 0; i < 8; i++) bs += red[i];
    float inv = 1.f / bs;
    a.x*=inv; a.y*=inv; a.z*=inv; a.w*=inv;
    b.x*=inv; b.y*=inv; b.z*=inv; b.w*=inv;
    *(float4*)(pr + tid*8)     = a;
    *(float4*)(pr + tid*8 + 4) = b;
}

// ---------------- bits: warp per row ----------------
__global__ void bits_kernel(const float* __restrict__ sel, const float* __restrict__ w,
                            const float* __restrict__ b0,
                            float* __restrict__ pairs_out, float* __restrict__ bits_sc) {
    int wid = threadIdx.x >> 5, lane = threadIdx.x & 31;
    float4 w0 = *(const float4*)(w + lane*8);
    float4 w1 = *(const float4*)(w + lane*8 + 4);
    float bias = b0[0];
    for (int rr = wid; rr < B_*NQ_; rr += 16) {
        const float* sr = sel + (size_t)rr * D_ + lane*8;
        float4 a = *(const float4*)(sr);
        float4 b = *(const float4*)(sr + 4);
        float s = a.x*w0.x + a.y*w0.y + a.z*w0.z + a.w*w0.w
                + b.x*w1.x + b.y*w1.y + b.z*w1.z + b.w*w1.w;
        #pragma unroll
        for (int o = 16; o > 0; o >>= 1) s += __shfl_xor_sync(0xffffffffu, s, o);
        if (lane == 0) {
            float bit = 1.f / (1.f + expf(-(s + bias)));
            pairs_out[rr] = bit;
            bits_sc[rr]   = bit;
        }
    }
}

// ---------------- sequential MLP scan (w2 column in registers) ----------------
__global__ void scan_kernel(const float* __restrict__ pairs,
                            const float* __restrict__ w1, const float* __restrict__ b1,
                            const float* __restrict__ w2, const float* __restrict__ b2,
                            const float* __restrict__ w3, const float* __restrict__ b3,
                            float* __restrict__ sum_all) {
    int tid = threadIdx.x;
    int bb = tid >> 6, u = tid & 63;
    __shared__ float h1[4][65];
    __shared__ float h2s[4][65];
    __shared__ float carry[4];
    float w2r[64];
    #pragma unroll
    for (int j = 0; j < 64; j++) w2r[j] = w2[j*64 + u];
    float w1a = w1[u], w1b = w1[64+u], w1c = w1[128+u];
    float b1u = b1[u], b2u = b2[u];
    if (u == 0) carry[bb] = 0.f;
    __syncthreads();
    for (int step = 0; step < 64; step++) {
        float a  = pairs[bb*128 + step*2 + 0];
        float bv = pairs[bb*128 + step*2 + 1];
        float cz = carry[bb];
        float h = a*w1a + bv*w1b + cz*w1c + b1u;
        h1[bb][u] = fmaxf(h, 0.f);
        __syncthreads();
        float h2 = b2u;
        #pragma unroll 16
        for (int j = 0; j < 64; j++) h2 += h1[bb][j] * w2r[j];
        h2s[bb][u] = fmaxf(h2, 0.f);
        __syncthreads();
        if (u < 2) {
            float o = b3[u];
            #pragma unroll 16
            for (int j = 0; j < 64; j++) o += h2s[bb][j] * w3[j*2+u];
            o = 1.f / (1.f + expf(-o));
            if (u == 0) sum_all[bb*65 + step] = o;
            else        carry[bb] = o;
        }
        __syncthreads();
    }
    if (u == 0) sum_all[bb*65 + 64] = carry[bb];
}

// ---------------- host launcher ----------------
extern "C" void kernel_launch(void* const* d_in, const int* in_sizes, int n_in,
                              void* d_out, int out_size) {
    const int*   tokens = (const int*)  d_in[0];
    const float* embedw = (const float*)d_in[1];
    const float* ln1_w  = (const float*)d_in[2];
    const float* ln1_b  = (const float*)d_in[3];
    const float* qkv_w  = (const float*)d_in[4];
    const float* qkv_b  = (const float*)d_in[5];
    const float* proj_w = (const float*)d_in[6];
    const float* proj_b = (const float*)d_in[7];
    const float* ln2_w  = (const float*)d_in[8];
    const float* ln2_b  = (const float*)d_in[9];
    const float* ffn1_w = (const float*)d_in[10];
    const float* ffn1_b = (const float*)d_in[11];
    const float* ffn2_w = (const float*)d_in[12];
    const float* ffn2_b = (const float*)d_in[13];
    const float* lnf_w  = (const float*)d_in[14];
    const float* lnf_b  = (const float*)d_in[15];
    const float* oq     = (const float*)d_in[16];
    const float* outp_w = (const float*)d_in[17];
    const float* outp_b = (const float*)d_in[18];
    const float* mlp_w1 = (const float*)d_in[19];
    const float* mlp_b1 = (const float*)d_in[20];
    const float* mlp_w2 = (const float*)d_in[21];
    const float* mlp_b2 = (const float*)d_in[22];
    const float* mlp_w3 = (const float*)d_in[23];
    const float* mlp_b3 = (const float*)d_in[24];

    float* out       = (float*)d_out;
    float* out_sum   = out;
    float* out_pairs = out + 260;
    float* out_p     = out + 772;

    float *x, *h, *qkv, *ffn, *sel, *oqT, *bits;
    unsigned *qkb, *vT;
    float4* ropec;
    cudaGetSymbolAddress((void**)&x,     g_x);
    cudaGetSymbolAddress((void**)&h,     g_h);
    cudaGetSymbolAddress((void**)&qkv,   g_qkv);
    cudaGetSymbolAddress((void**)&qkb,   g_qkb);
    cudaGetSymbolAddress((void**)&vT,    g_vTb);
    cudaGetSymbolAddress((void**)&ffn,   g_ffn);
    cudaGetSymbolAddress((void**)&sel,   g_sel);
    cudaGetSymbolAddress((void**)&ropec, g_ropec);
    cudaGetSymbolAddress((void**)&oqT,   g_oqT);
    cudaGetSymbolAddress((void**)&bits,  g_bits);

    cudaFuncSetAttribute(attn_bf16_kernel, cudaFuncAttributeMaxDynamicSharedMemorySize, ATTN_SMEM4);

    const int M = B_*T_;

    rope_tab_kernel<<<(T_*16 + 255)/256, 256>>>(ropec);
    oqT_kernel<<<(NQ_*D_ + 255)/256, 256>>>(oq, oqT);
    embed_kernel<<<(B_*T_*D_ + 255)/256, 256>>>(tokens, embedw, x);

    for (int l = 0; l < L_; l++) {
        ln_kernel<<<M/8, 256>>>(x, ln1_w + l*D_, ln1_b + l*D_, h);
        gemm_tf32_kernel<0,false><<<dim3(6, 64), 256>>>(
            h, qkv_w + (size_t)l*D_*3*D_, qkv_b + l*3*D_, nullptr, qkv, M, 3*D_, D_, 1.f, 0,0,0);
        ropevt_kernel<<<dim3(T_/64, H_, B_), 256>>>(qkv, ropec, qkb, vT);
        attn_bf16_kernel<<<dim3(T_/128, H_, B_), 256, ATTN_SMEM4>>>(qkb, vT, h);
        gemm_tf32_kernel<0,true><<<dim3(2, 64), 256>>>(
            h, proj_w + (size_t)l*D_*D_, proj_b + l*D_, x, x, M, D_, D_, 1.f, 0,0,0);
        ln_kernel<<<M/8, 256>>>(x, ln2_w + l*D_, ln2_b + l*D_, h);
        gemm_tf32_kernel<1,false><<<dim3(8, 64), 256>>>(
            h, ffn1_w + (size_t)l*D_*4*D_, ffn1_b + l*4*D_, nullptr, ffn, M, 4*D_, D_, 1.f, 0,0,0);
        gemm_tf32_kernel<0,true><<<dim3(2, 64), 256>>>(
            ffn, ffn2_w + (size_t)l*4*D_*D_, ffn2_b + l*D_, x, x, M, D_, 4*D_, 1.f, 0,0,0);
    }

    ln_kernel<<<M/8, 256>>>(x, lnf_w, lnf_b, h);

    // scores -> out_p[b][q][t] (transposed epilogue), softmax rows in place
    gemm_tf32_kernel<3,false><<<dim3(1, 64), 256>>>(
        h, oqT, nullptr, nullptr, out_p, M, NQ_, D_, 0.0625f, 0,0,0);
    qsoftmax_rows<<<B_*NQ_, 256>>>(out_p);
    // selected = p @ xf  (batched GEMM: M=128, N=256, K=2048)
    gemm_tf32_kernel<0,false><<<dim3(2, 1, 4), 256>>>(
        out_p, h, nullptr, nullptr, sel, NQ_, D_, T_, 1.f,
        (size_t)NQ_*T_, (size_t)T_*D_, (size_t)NQ_*D_);
    bits_kernel<<<1, 512>>>(sel, outp_w, outp_b, out_pairs, bits);
    scan_kernel<<<1, 256>>>(bits, mlp_w1, mlp_b1, mlp_w2, mlp_b2, mlp_w3, mlp_b3, out_sum);
}

// round 12
// speedup vs baseline: 1.3055x; 1.3055x over previous
#include <cuda_runtime.h>
#include <cuda_bf16.h>
#include <cuda_fp16.h>
#include <math.h>

#define B_ 4
#define T_ 2048
#define D_ 256
#define H_ 4
#define HD_ 64
#define L_ 2
#define NQ_ 128

// ---------------- device scratch ----------------
__device__ float g_x  [B_*T_*D_];
__device__ float g_h  [B_*T_*D_];
__device__ float g_qkv[B_*T_*3*D_];
__device__ float g_ffn[(size_t)B_*T_*4*D_];
__device__ float g_sel[B_*NQ_*D_];
__device__ float g_qs [(size_t)B_*T_*NQ_];
__device__ float g_oqT[D_*NQ_];
__device__ float g_bits[B_*NQ_];

// ---------------- helpers ----------------
__device__ __forceinline__ unsigned f2tf(float f) {
    unsigned u; asm("cvt.rna.tf32.f32 %0, %1;" : "=r"(u) : "f"(f)); return u;
}
__device__ __forceinline__ unsigned pkbf(float lo, float hi) {
    unsigned r; asm("cvt.rn.bf16x2.f32 %0, %1, %2;" : "=r"(r) : "f"(hi), "f"(lo)); return r;
}
__device__ __forceinline__ unsigned pkhf(float lo, float hi) {
    unsigned r; asm("cvt.rn.f16x2.f32 %0, %1, %2;" : "=r"(r) : "f"(hi), "f"(lo)); return r;
}
__device__ __forceinline__ unsigned ex2h2(unsigned x) {
    unsigned r; asm("ex2.approx.f16x2 %0, %1;" : "=r"(r) : "r"(x)); return r;
}
__device__ __forceinline__ float2 h22f2(unsigned x) {
    __half2 h = *reinterpret_cast<__half2*>(&x);
    return __half22float2(h);
}
__device__ __forceinline__ void mma_tf32(float* c, const unsigned* a, const unsigned* b) {
    asm volatile("mma.sync.aligned.m16n8k8.row.col.f32.tf32.tf32.f32 "
        "{%0,%1,%2,%3}, {%4,%5,%6,%7}, {%8,%9}, {%0,%1,%2,%3};"
        : "+f"(c[0]), "+f"(c[1]), "+f"(c[2]), "+f"(c[3])
        : "r"(a[0]), "r"(a[1]), "r"(a[2]), "r"(a[3]), "r"(b[0]), "r"(b[1]));
}
__device__ __forceinline__ void mma_bf16(float* c, const unsigned* a, const unsigned* b) {
    asm volatile("mma.sync.aligned.m16n8k16.row.col.f32.bf16.bf16.f32 "
        "{%0,%1,%2,%3}, {%4,%5,%6,%7}, {%8,%9}, {%0,%1,%2,%3};"
        : "+f"(c[0]), "+f"(c[1]), "+f"(c[2]), "+f"(c[3])
        : "r"(a[0]), "r"(a[1]), "r"(a[2]), "r"(a[3]), "r"(b[0]), "r"(b[1]));
}
__device__ __forceinline__ void mma_f16(float* c, const unsigned* a, const unsigned* b) {
    asm volatile("mma.sync.aligned.m16n8k16.row.col.f32.f16.f16.f32 "
        "{%0,%1,%2,%3}, {%4,%5,%6,%7}, {%8,%9}, {%0,%1,%2,%3};"
        : "+f"(c[0]), "+f"(c[1]), "+f"(c[2]), "+f"(c[3])
        : "r"(a[0]), "r"(a[1]), "r"(a[2]), "r"(a[3]), "r"(b[0]), "r"(b[1]));
}

// ---------------- embed ----------------
__global__ void embed_kernel(const int* __restrict__ tokens,
                             const float* __restrict__ emb,
                             float* __restrict__ x) {
    int i = blockIdx.x * 256 + threadIdx.x;
    if (i >= B_*T_*D_) return;
    int d = i & (D_-1);
    int bt = i >> 8;
    x[i] = emb[tokens[bt]*D_ + d];
}

// ---------------- layernorm: warp per row ----------------
__global__ void ln_kernel(const float* __restrict__ x,
                          const float* __restrict__ w,
                          const float* __restrict__ b,
                          float* __restrict__ y) {
    int row = blockIdx.x * 8 + (threadIdx.x >> 5);
    int lane = threadIdx.x & 31;
    const float* xr = x + (size_t)row * D_;
    float4 v0 = *(const float4*)(xr + lane*4);
    float4 v1 = *(const float4*)(xr + 128 + lane*4);
    float s = v0.x+v0.y+v0.z+v0.w + v1.x+v1.y+v1.z+v1.w;
    #pragma unroll
    for (int o = 16; o > 0; o >>= 1) s += __shfl_xor_sync(0xffffffffu, s, o);
    float mean = s * (1.f/256.f);
    float d0=v0.x-mean, d1=v0.y-mean, d2=v0.z-mean, d3=v0.w-mean;
    float d4=v1.x-mean, d5=v1.y-mean, d6=v1.z-mean, d7=v1.w-mean;
    float s2 = d0*d0+d1*d1+d2*d2+d3*d3+d4*d4+d5*d5+d6*d6+d7*d7;
    #pragma unroll
    for (int o = 16; o > 0; o >>= 1) s2 += __shfl_xor_sync(0xffffffffu, s2, o);
    float rs = rsqrtf(s2 * (1.f/256.f) + 1e-5f);
    float4 w0 = *(const float4*)(w + lane*4), w1 = *(const float4*)(w + 128 + lane*4);
    float4 b0 = *(const float4*)(b + lane*4), b1 = *(const float4*)(b + 128 + lane*4);
    float* yr = y + (size_t)row * D_;
    *(float4*)(yr + lane*4)       = make_float4(d0*rs*w0.x+b0.x, d1*rs*w0.y+b0.y, d2*rs*w0.z+b0.z, d3*rs*w0.w+b0.w);
    *(float4*)(yr + 128 + lane*4) = make_float4(d4*rs*w1.x+b1.x, d5*rs*w1.y+b1.y, d6*rs*w1.z+b1.z, d7*rs*w1.w+b1.w);
}

// ---------------- tf32 tensor-core GEMM (R6-proven) ----------------
template<int ACT, bool RES>
__global__ __launch_bounds__(256)
void gemm_tf32_kernel(const float* __restrict__ A, const float* __restrict__ W,
                      const float* __restrict__ bias, const float* __restrict__ resid,
                      float* __restrict__ C, int M, int N, int K, float alpha) {
    __shared__ unsigned Ast[2][16][132];
    __shared__ unsigned Ws [2][16][132];
    int tid = threadIdx.x;
    int w = tid >> 5, lane = tid & 31;
    int g = lane >> 2, q = lane & 3;
    int wm = (w >> 2) * 64, wn = (w & 3) * 32;
    int bm = blockIdx.y * 128, bn = blockIdx.x * 128;

    float acc[4][4][4] = {};
    float4 aR[2], bR[2];

    #pragma unroll
    for (int i = 0; i < 2; i++) {
        int fi = tid + i*256;
        int r = fi >> 2, kg = (fi & 3) << 2;
        aR[i] = *(const float4*)(A + (size_t)(bm + r) * K + kg);
        int r2 = fi >> 5, cg = (fi & 31) << 2;
        bR[i] = *(const float4*)(W + (size_t)r2 * N + bn + cg);
    }
    #pragma unroll
    for (int i = 0; i < 2; i++) {
        int fi = tid + i*256;
        int r = fi >> 2, kg = (fi & 3) << 2;
        Ast[0][kg+0][r] = f2tf(aR[i].x); Ast[0][kg+1][r] = f2tf(aR[i].y);
        Ast[0][kg+2][r] = f2tf(aR[i].z); Ast[0][kg+3][r] = f2tf(aR[i].w);
        int r2 = fi >> 5, cg = (fi & 31) << 2;
        Ws[0][r2][cg+0] = f2tf(bR[i].x); Ws[0][r2][cg+1] = f2tf(bR[i].y);
        Ws[0][r2][cg+2] = f2tf(bR[i].z); Ws[0][r2][cg+3] = f2tf(bR[i].w);
    }
    __syncthreads();

    int nT = K >> 4;
    for (int t = 0; t < nT; t++) {
        int cur = t & 1;
        if (t + 1 < nT) {
            int k0 = (t + 1) << 4;
            #pragma unroll
            for (int i = 0; i < 2; i++) {
                int fi = tid + i*256;
                int r = fi >> 2, kg = (fi & 3) << 2;
                aR[i] = *(const float4*)(A + (size_t)(bm + r) * K + k0 + kg);
                int r2 = fi >> 5, cg = (fi & 31) << 2;
                bR[i] = *(const float4*)(W + (size_t)(k0 + r2) * N + bn + cg);
            }
        }
        #pragma unroll
        for (int ks = 0; ks < 16; ks += 8) {
            unsigned af[4][4], bf[4][2];
            #pragma unroll
            for (int mf = 0; mf < 4; mf++) {
                int r0 = wm + mf*16;
                af[mf][0] = Ast[cur][ks+q  ][r0+g  ];
                af[mf][1] = Ast[cur][ks+q  ][r0+g+8];
                af[mf][2] = Ast[cur][ks+q+4][r0+g  ];
                af[mf][3] = Ast[cur][ks+q+4][r0+g+8];
            }
            #pragma unroll
            for (int nf = 0; nf < 4; nf++) {
                int c0 = wn + nf*8;
                bf[nf][0] = Ws[cur][ks+q  ][c0+g];
                bf[nf][1] = Ws[cur][ks+q+4][c0+g];
            }
            #pragma unroll
            for (int mf = 0; mf < 4; mf++)
                #pragma unroll
                for (int nf = 0; nf < 4; nf++)
                    mma_tf32(acc[mf][nf], af[mf], bf[nf]);
        }
        if (t + 1 < nT) {
            int nb = cur ^ 1;
            #pragma unroll
            for (int i = 0; i < 2; i++) {
                int fi = tid + i*256;
                int r = fi >> 2, kg = (fi & 3) << 2;
                Ast[nb][kg+0][r] = f2tf(aR[i].x); Ast[nb][kg+1][r] = f2tf(aR[i].y);
                Ast[nb][kg+2][r] = f2tf(aR[i].z); Ast[nb][kg+3][r] = f2tf(aR[i].w);
                int r2 = fi >> 5, cg = (fi & 31) << 2;
                Ws[nb][r2][cg+0] = f2tf(bR[i].x); Ws[nb][r2][cg+1] = f2tf(bR[i].y);
                Ws[nb][r2][cg+2] = f2tf(bR[i].z); Ws[nb][r2][cg+3] = f2tf(bR[i].w);
            }
        }
        __syncthreads();
    }

    #pragma unroll
    for (int mf = 0; mf < 4; mf++) {
        #pragma unroll
        for (int i = 0; i < 2; i++) {
            int r = bm + wm + mf*16 + g + i*8;
            #pragma unroll
            for (int nf = 0; nf < 4; nf++) {
                int c = bn + wn + nf*8 + 2*q;
                float v0 = acc[mf][nf][i*2+0] * alpha + (bias ? bias[c]   : 0.f);
                float v1 = acc[mf][nf][i*2+1] * alpha + (bias ? bias[c+1] : 0.f);
                if (ACT == 1) {
                    v0 = 0.5f * v0 * (1.f + erff(v0 * 0.70710678118654752f));
                    v1 = 0.5f * v1 * (1.f + erff(v1 * 0.70710678118654752f));
                }
                if (RES) {
                    v0 += resid[(size_t)r * N + c];
                    v1 += resid[(size_t)r * N + c + 1];
                }
                *(float2*)(C + (size_t)r * N + c) = make_float2(v0, v1);
            }
        }
    }
}

// ---------------- RoPE ----------------
__global__ void rope_kernel(float* __restrict__ qkv) {
    int idx = blockIdx.x * 256 + threadIdx.x;
    if (idx >= B_*T_*H_*32) return;
    int d = idx & 31;
    int h = (idx >> 5) & (H_-1);
    int bt = idx >> 7;
    int t = bt & (T_-1);
    float invf = powf(10000.f, -(float)d * (1.f/32.f));
    float ang = (float)t * invf;
    float sv, cv;
    sincosf(ang, &sv, &cv);
    float* base = qkv + (size_t)bt * (3*D_);
    float* qp = base + h * HD_;
    float q1 = qp[d], q2 = qp[d+32];
    qp[d]    = q1*cv - q2*sv;
    qp[d+32] = q2*cv + q1*sv;
    float* kp = base + D_ + h * HD_;
    float k1 = kp[d], k2 = kp[d+32];
    kp[d]    = k1*cv - k2*sv;
    kp[d+32] = k2*cv + k1*sv;
}

// ---------------- bf16/f16 flash attention: packed-half2 exp (MUFU halved) ----------------
// grid (T/64, H, B), 128 threads (4 warps x 16 rows). QK bf16, exp f16x2, PV f16.
__global__ __launch_bounds__(128)
void attn_bf16_kernel(const float* __restrict__ qkv, float* __restrict__ out) {
    __shared__ unsigned Qw[64*36], Kw[64*36], Vw[64*36];
    int qt = (T_/64 - 1) - blockIdx.x;       // heavy blocks first
    int h = blockIdx.y, b = blockIdx.z;
    int tid = threadIdx.x;
    int w = tid >> 5, lane = tid & 31, g = lane >> 2, q = lane & 3;
    int r0 = w * 16;
    const float L2E = 1.4426950408889634f;

    // load Q tile -> bf16
    const float* qg = qkv + ((size_t)(b*T_) + qt*64) * (3*D_) + h*HD_;
    #pragma unroll
    for (int i = 0; i < 8; i++) {
        int idx = tid + i*128;
        int r = idx >> 4, cg = (idx & 15) << 2;
        float4 v = *(const float4*)(qg + (size_t)r * (3*D_) + cg);
        *(uint2*)&Qw[r*36 + (cg >> 1)] = make_uint2(pkbf(v.x, v.y), pkbf(v.z, v.w));
    }

    float m0 = -INFINITY, m1 = -INFINITY;
    float l0 = 0.f, l1 = 0.f;
    float O[8][4] = {};
    int vd = tid & 63, vsg = (tid >> 6) * 32;

    for (int kt = 0; kt <= qt; kt++) {
        __syncthreads();   // prior reads done before overwrite (also covers Q stores, iter 0)
        const float* kg = qkv + ((size_t)(b*T_) + kt*64) * (3*D_) + D_ + h*HD_;
        #pragma unroll
        for (int i = 0; i < 8; i++) {
            int idx = tid + i*128;
            int r = idx >> 4, cg = (idx & 15) << 2;
            float4 v = *(const float4*)(kg + (size_t)r * (3*D_) + cg);
            *(uint2*)&Kw[r*36 + (cg >> 1)] = make_uint2(pkbf(v.x, v.y), pkbf(v.z, v.w));
        }
        // V transposed: VT[d][s], packed f16
        const float* vg = qkv + ((size_t)(b*T_) + kt*64) * (3*D_) + 2*D_ + h*HD_ + vd;
        #pragma unroll
        for (int so = 0; so < 16; so++) {
            int s = vsg + so*2;
            float a = vg[(size_t)s * (3*D_)];
            float c = vg[(size_t)(s+1) * (3*D_)];
            Vw[vd*36 + (s >> 1)] = pkhf(a, c);
        }
        __syncthreads();

        // S = Q K^T  (bf16 k16)
        float S[8][4] = {};
        #pragma unroll
        for (int ss = 0; ss < 4; ss++) {
            unsigned af[4];
            af[0] = Qw[(r0+g  )*36 + ss*8 + q    ];
            af[1] = Qw[(r0+g+8)*36 + ss*8 + q    ];
            af[2] = Qw[(r0+g  )*36 + ss*8 + q + 4];
            af[3] = Qw[(r0+g+8)*36 + ss*8 + q + 4];
            #pragma unroll
            for (int nf = 0; nf < 8; nf++) {
                unsigned bf[2];
                bf[0] = Kw[(nf*8+g)*36 + ss*8 + q    ];
                bf[1] = Kw[(nf*8+g)*36 + ss*8 + q + 4];
                mma_bf16(S[nf], af, bf);
            }
        }

        int ra = r0 + g, rb2 = ra + 8;
        #pragma unroll
        for (int nf = 0; nf < 8; nf++) {
            int c = nf*8 + 2*q;
            S[nf][0] *= 0.125f; S[nf][1] *= 0.125f;
            S[nf][2] *= 0.125f; S[nf][3] *= 0.125f;
            if (kt == qt) {
                if (c   > ra ) S[nf][0] = -INFINITY;
                if (c+1 > ra ) S[nf][1] = -INFINITY;
                if (c   > rb2) S[nf][2] = -INFINITY;
                if (c+1 > rb2) S[nf][3] = -INFINITY;
            }
        }
        float mxa = -INFINITY, mxb = -INFINITY;
        #pragma unroll
        for (int nf = 0; nf < 8; nf++) {
            mxa = fmaxf(mxa, fmaxf(S[nf][0], S[nf][1]));
            mxb = fmaxf(mxb, fmaxf(S[nf][2], S[nf][3]));
        }
        mxa = fmaxf(mxa, __shfl_xor_sync(0xffffffffu, mxa, 1));
        mxa = fmaxf(mxa, __shfl_xor_sync(0xffffffffu, mxa, 2));
        mxb = fmaxf(mxb, __shfl_xor_sync(0xffffffffu, mxb, 1));
        mxb = fmaxf(mxb, __shfl_xor_sync(0xffffffffu, mxb, 2));
        float nm0 = fmaxf(m0, mxa), nm1 = fmaxf(m1, mxb);
        float rf0 = __expf(m0 - nm0), rf1 = __expf(m1 - nm1);

        // packed f16x2 exp: E0 = exp row rg0 pairs, E1 = exp row rg1 pairs
        float nm0l = nm0 * L2E, nm1l = nm1 * L2E;
        unsigned E0[8], E1[8];
        float sa = 0.f, sb = 0.f;
        #pragma unroll
        for (int nf = 0; nf < 8; nf++) {
            float y0 = fmaf(S[nf][0], L2E, -nm0l);
            float y1 = fmaf(S[nf][1], L2E, -nm0l);
            float y2 = fmaf(S[nf][2], L2E, -nm1l);
            float y3 = fmaf(S[nf][3], L2E, -nm1l);
            E0[nf] = ex2h2(pkhf(y0, y1));
            E1[nf] = ex2h2(pkhf(y2, y3));
            float2 e0 = h22f2(E0[nf]);
            float2 e1 = h22f2(E1[nf]);
            sa += e0.x + e0.y;
            sb += e1.x + e1.y;
        }
        sa += __shfl_xor_sync(0xffffffffu, sa, 1);
        sa += __shfl_xor_sync(0xffffffffu, sa, 2);
        sb += __shfl_xor_sync(0xffffffffu, sb, 1);
        sb += __shfl_xor_sync(0xffffffffu, sb, 2);
        l0 = l0 * rf0 + sa;  l1 = l1 * rf1 + sb;
        m0 = nm0;            m1 = nm1;
        #pragma unroll
        for (int nf = 0; nf < 8; nf++) {
            O[nf][0] *= rf0; O[nf][1] *= rf0;
            O[nf][2] *= rf1; O[nf][3] *= rf1;
        }

        // O += P V : P = exp words directly (f16), B from V^T (f16)
        #pragma unroll
        for (int ss = 0; ss < 4; ss++) {
            unsigned pa[4];
            pa[0] = E0[2*ss  ];
            pa[1] = E1[2*ss  ];
            pa[2] = E0[2*ss+1];
            pa[3] = E1[2*ss+1];
            #pragma unroll
            for (int nf = 0; nf < 8; nf++) {
                unsigned bf[2];
                bf[0] = Vw[(nf*8+g)*36 + ss*8 + q    ];
                bf[1] = Vw[(nf*8+g)*36 + ss*8 + q + 4];
                mma_f16(O[nf], pa, bf);
            }
        }
    }

    float inv0 = 1.f / l0, inv1 = 1.f / l1;
    float* ob = out + ((size_t)(b*T_) + qt*64 + r0 + g) * D_ + h*HD_;
    #pragma unroll
    for (int nf = 0; nf < 8; nf++) {
        int c = nf*8 + 2*q;
        *(float2*)(ob + c)        = make_float2(O[nf][0]*inv0, O[nf][1]*inv0);
        *(float2*)(ob + 8*D_ + c) = make_float2(O[nf][2]*inv1, O[nf][3]*inv1);
    }
}

// ---------------- oq transpose [128][256] -> [256][128] ----------------
__global__ void oqT_kernel(const float* __restrict__ oq, float* __restrict__ oqT) {
    int idx = blockIdx.x * 256 + threadIdx.x;
    if (idx >= NQ_*D_) return;
    int r = idx >> 8, c = idx & 255;
    oqT[c*NQ_ + r] = oq[idx];
}

// ---------------- query softmax ----------------
__global__ void qsoftmax_kernel(const float* __restrict__ scores, float* __restrict__ p) {
    int bq = blockIdx.x;
    int b = bq >> 7, q = bq & 127;
    int tid = threadIdx.x;
    __shared__ float red[8];
    float vals[8];
    float lmax = -INFINITY;
    #pragma unroll
    for (int i = 0; i < 8; i++) {
        int t = tid + i*256;
        float s = scores[(size_t)(b*T_ + t) * NQ_ + q];
        vals[i] = s;
        lmax = fmaxf(lmax, s);
    }
    #pragma unroll
    for (int o = 16; o > 0; o >>= 1) lmax = fmaxf(lmax, __shfl_xor_sync(0xffffffffu, lmax, o));
    if ((tid & 31) == 0) red[tid >> 5] = lmax;
    __syncthreads();
    float bmax = -INFINITY;
    #pragma unroll
    for (int i = 0; i < 8; i++) bmax = fmaxf(bmax, red[i]);
    float lsum = 0.f;
    #pragma unroll
    for (int i = 0; i < 8; i++) { vals[i] = expf(vals[i] - bmax); lsum += vals[i]; }
    __syncthreads();
    #pragma unroll
    for (int o = 16; o > 0; o >>= 1) lsum += __shfl_xor_sync(0xffffffffu, lsum, o);
    if ((tid & 31) == 0) red[tid >> 5] = lsum;
    __syncthreads();
    float bsum = 0.f;
    #pragma unroll
    for (int i = 0; i < 8; i++) bsum += red[i];
    float inv = 1.f / bsum;
    #pragma unroll
    for (int i = 0; i < 8; i++)
        p[(size_t)bq * T_ + tid + i*256] = vals[i] * inv;
}

// ---------------- selected ----------------
__global__ void selected_kernel(const float* __restrict__ xf, const float* __restrict__ p,
                                float* __restrict__ sel) {
    int blk = blockIdx.x;
    int b = blk >> 4, qg = (blk & 15) * 8;
    int d = threadIdx.x;
    __shared__ float ps[8][257];
    float acc[8] = {};
    for (int t0 = 0; t0 < T_; t0 += 256) {
        #pragma unroll
        for (int g = 0; g < 8; g++)
            ps[g][threadIdx.x] = p[(size_t)(b*NQ_ + qg + g) * T_ + t0 + threadIdx.x];
        __syncthreads();
        for (int tt = 0; tt < 256; tt++) {
            float xv = xf[(size_t)(b*T_ + t0 + tt) * D_ + d];
            #pragma unroll
            for (int g = 0; g < 8; g++) acc[g] += ps[g][tt] * xv;
        }
        __syncthreads();
    }
    #pragma unroll
    for (int g = 0; g < 8; g++)
        sel[(size_t)(b*NQ_ + qg + g) * D_ + d] = acc[g];
}

// ---------------- bits ----------------
__global__ void bits_kernel(const float* __restrict__ sel, const float* __restrict__ w,
                            const float* __restrict__ b0,
                            float* __restrict__ pairs_out, float* __restrict__ bits_sc) {
    int i = threadIdx.x;
    float s = b0[0];
    const float* sr = sel + (size_t)i * D_;
    for (int d = 0; d < D_; d++) s += sr[d] * w[d];
    float bit = 1.f / (1.f + expf(-s));
    pairs_out[i] = bit;
    bits_sc[i] = bit;
}

// ---------------- sequential MLP scan ----------------
__global__ void scan_kernel(const float* __restrict__ pairs,
                            const float* __restrict__ w1, const float* __restrict__ b1,
                            const float* __restrict__ w2, const float* __restrict__ b2,
                            const float* __restrict__ w3, const float* __restrict__ b3,
                            float* __restrict__ sum_all) {
    int tid = threadIdx.x;
    int bb = tid >> 6, u = tid & 63;
    __shared__ float h1[4][65];
    __shared__ float h2s[4][65];
    __shared__ float carry[4];
    if (u == 0) carry[bb] = 0.f;
    __syncthreads();
    for (int step = 0; step < 64; step++) {
        float a  = pairs[bb*128 + step*2 + 0];
        float bv = pairs[bb*128 + step*2 + 1];
        float cz = carry[bb];
        float h = a*w1[0*64+u] + bv*w1[1*64+u] + cz*w1[2*64+u] + b1[u];
        h1[bb][u] = fmaxf(h, 0.f);
        __syncthreads();
        float h2 = b2[u];
        #pragma unroll 8
        for (int j = 0; j < 64; j++) h2 += h1[bb][j] * w2[j*64+u];
        h2s[bb][u] = fmaxf(h2, 0.f);
        __syncthreads();
        if (u < 2) {
            float o = b3[u];
            #pragma unroll 8
            for (int j = 0; j < 64; j++) o += h2s[bb][j] * w3[j*2+u];
            o = 1.f / (1.f + expf(-o));
            if (u == 0) sum_all[bb*65 + step] = o;
            else        carry[bb] = o;
        }
        __syncthreads();
    }
    if (u == 0) sum_all[bb*65 + 64] = carry[bb];
}

// ---------------- host launcher ----------------
extern "C" void kernel_launch(void* const* d_in, const int* in_sizes, int n_in,
                              void* d_out, int out_size) {
    const int*   tokens = (const int*)  d_in[0];
    const float* embedw = (const float*)d_in[1];
    const float* ln1_w  = (const float*)d_in[2];
    const float* ln1_b  = (const float*)d_in[3];
    const float* qkv_w  = (const float*)d_in[4];
    const float* qkv_b  = (const float*)d_in[5];
    const float* proj_w = (const float*)d_in[6];
    const float* proj_b = (const float*)d_in[7];
    const float* ln2_w  = (const float*)d_in[8];
    const float* ln2_b  = (const float*)d_in[9];
    const float* ffn1_w = (const float*)d_in[10];
    const float* ffn1_b = (const float*)d_in[11];
    const float* ffn2_w = (const float*)d_in[12];
    const float* ffn2_b = (const float*)d_in[13];
    const float* lnf_w  = (const float*)d_in[14];
    const float* lnf_b  = (const float*)d_in[15];
    const float* oq     = (const float*)d_in[16];
    const float* outp_w = (const float*)d_in[17];
    const float* outp_b = (const float*)d_in[18];
    const float* mlp_w1 = (const float*)d_in[19];
    const float* mlp_b1 = (const float*)d_in[20];
    const float* mlp_w2 = (const float*)d_in[21];
    const float* mlp_b2 = (const float*)d_in[22];
    const float* mlp_w3 = (const float*)d_in[23];
    const float* mlp_b3 = (const float*)d_in[24];

    float* out       = (float*)d_out;
    float* out_sum   = out;
    float* out_pairs = out + 260;
    float* out_p     = out + 772;

    float *x, *h, *qkv, *ffn, *sel, *qs, *oqT, *bits;
    cudaGetSymbolAddress((void**)&x,    g_x);
    cudaGetSymbolAddress((void**)&h,    g_h);
    cudaGetSymbolAddress((void**)&qkv,  g_qkv);
    cudaGetSymbolAddress((void**)&ffn,  g_ffn);
    cudaGetSymbolAddress((void**)&sel,  g_sel);
    cudaGetSymbolAddress((void**)&qs,   g_qs);
    cudaGetSymbolAddress((void**)&oqT,  g_oqT);
    cudaGetSymbolAddress((void**)&bits, g_bits);

    const int M = B_*T_;

    oqT_kernel<<<(NQ_*D_ + 255)/256, 256>>>(oq, oqT);
    embed_kernel<<<(B_*T_*D_ + 255)/256, 256>>>(tokens, embedw, x);

    for (int l = 0; l < L_; l++) {
        ln_kernel<<<M/8, 256>>>(x, ln1_w + l*D_, ln1_b + l*D_, h);
        gemm_tf32_kernel<0,false><<<dim3(6, 64), 256>>>(
            h, qkv_w + (size_t)l*D_*3*D_, qkv_b + l*3*D_, nullptr, qkv, M, 3*D_, D_, 1.f);
        rope_kernel<<<(B_*T_*H_*32 + 255)/256, 256>>>(qkv);
        attn_bf16_kernel<<<dim3(T_/64, H_, B_), 128>>>(qkv, h);
        gemm_tf32_kernel<0,true><<<dim3(2, 64), 256>>>(
            h, proj_w + (size_t)l*D_*D_, proj_b + l*D_, x, x, M, D_, D_, 1.f);
        ln_kernel<<<M/8, 256>>>(x, ln2_w + l*D_, ln2_b + l*D_, h);
        gemm_tf32_kernel<1,false><<<dim3(8, 64), 256>>>(
            h, ffn1_w + (size_t)l*D_*4*D_, ffn1_b + l*4*D_, nullptr, ffn, M, 4*D_, D_, 1.f);
        gemm_tf32_kernel<0,true><<<dim3(2, 64), 256>>>(
            ffn, ffn2_w + (size_t)l*4*D_*D_, ffn2_b + l*D_, x, x, M, D_, 4*D_, 1.f);
    }

    ln_kernel<<<M/8, 256>>>(x, lnf_w, lnf_b, h);

    gemm_tf32_kernel<0,false><<<dim3(1, 64), 256>>>(
        h, oqT, nullptr, nullptr, qs, M, NQ_, D_, 0.0625f);
    qsoftmax_kernel<<<B_*NQ_, 256>>>(qs, out_p);
    selected_kernel<<<B_*16, 256>>>(h, out_p, sel);
    bits_kernel<<<1, 512>>>(sel, outp_w, outp_b, out_pairs, bits);
    scan_kernel<<<1, 256>>>(bits, mlp_w1, mlp_b1, mlp_w2, mlp_b2, mlp_w3, mlp_b3, out_sum);
}